// round 15
// baseline (speedup 1.0000x reference)
#include <cuda_runtime.h>
#include <cuda_bf16.h>
#include <cstdint>
#include <math.h>

#define NN 2048
#define DD 768
#define HH 12
#define YY 64

#define NQT 32                 // q-tiles per head (qtile = 64 rows)
#define NGRP (HH * NQT)        // 384 (h, qt) groups
#define KSPLIT 2               // K-range halves per group
#define KCH (NN / KSPLIT / 128)// 8 chunks of 128 per CTA

// ---------------------------------------------------------------------------
// Scratch (__device__ globals; no allocation allowed)
// ---------------------------------------------------------------------------
__device__ __nv_bfloat16 g_gb [NN * DD];       // g in bf16
__device__ __nv_bfloat16 g_Wqb[HH * YY * DD];  // Wq in bf16
__device__ __nv_bfloat16 g_Wkb[HH * YY * DD];  // Wk in bf16
__device__ __nv_bfloat16 g_Q[HH * NN * YY];    // [h][n][y], pre-scaled by beta
__device__ __nv_bfloat16 g_K[HH * NN * YY];    // [h][n][y]
__device__ float2 g_ml[NGRP * KSPLIT * 64];    // per-row (m,l) per half
__device__ float g_partial[NGRP];              // per-group LSE row sums
__device__ unsigned int g_ticket2[NGRP];       // per-group pair election
__device__ unsigned int g_ticket;              // global last-group election

// ---------------------------------------------------------------------------
// Helpers (standard sm_80+ features: ldmatrix / mma.sync / cp.async)
// ---------------------------------------------------------------------------
__device__ __forceinline__ uint32_t smem_u32(const void* p) {
    uint32_t a;
    asm("{ .reg .u64 t; cvta.to.shared.u64 t, %1; cvt.u32.u64 %0, t; }" : "=r"(a) : "l"(p));
    return a;
}

__device__ __forceinline__ void cpa16(uint32_t dst, const void* src) {
    asm volatile("cp.async.cg.shared.global [%0], [%1], 16;" :: "r"(dst), "l"(src));
}
#define CP_COMMIT() asm volatile("cp.async.commit_group;" ::: "memory")
#define CP_WAIT(n)  asm volatile("cp.async.wait_group %0;" :: "n"(n) : "memory")

__device__ __forceinline__ void ldsm4(uint32_t& r0, uint32_t& r1, uint32_t& r2, uint32_t& r3,
                                      uint32_t addr) {
    asm volatile("ldmatrix.sync.aligned.m8n8.x4.shared.b16 {%0,%1,%2,%3}, [%4];"
                 : "=r"(r0), "=r"(r1), "=r"(r2), "=r"(r3) : "r"(addr));
}

__device__ __forceinline__ void mma16816(float* c, const uint32_t* a, uint32_t b0, uint32_t b1) {
    asm volatile(
        "mma.sync.aligned.m16n8k16.row.col.f32.bf16.bf16.f32 "
        "{%0,%1,%2,%3}, {%4,%5,%6,%7}, {%8,%9}, {%0,%1,%2,%3};"
        : "+f"(c[0]), "+f"(c[1]), "+f"(c[2]), "+f"(c[3])
        : "r"(a[0]), "r"(a[1]), "r"(a[2]), "r"(a[3]), "r"(b0), "r"(b1));
}

__device__ __forceinline__ uint32_t bf16x2(float hi, float lo) {
    uint32_t r;
    asm("cvt.rn.bf16x2.f32 %0, %1, %2;" : "=r"(r) : "f"(hi), "f"(lo));
    return r;
}

// ---------------------------------------------------------------------------
// Convert f32 inputs -> bf16 globals; reset tickets. (R8 version: max TLP)
// ---------------------------------------------------------------------------
#define NG8 (NN * DD / 8)          // 196608
#define NW8 (HH * YY * DD / 8)     // 73728

__global__ void __launch_bounds__(256) conv_kernel(const float* __restrict__ g,
                                                   const float* __restrict__ wq,
                                                   const float* __restrict__ wk)
{
    int i = blockIdx.x * 256 + threadIdx.x;
    if (i == 0) g_ticket = 0;
    if (i < NGRP) g_ticket2[i] = 0;
    const float* src;
    __nv_bfloat16* dst;
    int j;
    if (i < NG8)                { src = g;  dst = g_gb;  j = i; }
    else if (i < NG8 + NW8)     { src = wq; dst = g_Wqb; j = i - NG8; }
    else if (i < NG8 + 2 * NW8) { src = wk; dst = g_Wkb; j = i - NG8 - NW8; }
    else return;
    float4 v0 = *reinterpret_cast<const float4*>(src + (size_t)j * 8);
    float4 v1 = *reinterpret_cast<const float4*>(src + (size_t)j * 8 + 4);
    uint4 o;
    o.x = bf16x2(v0.y, v0.x);
    o.y = bf16x2(v0.w, v0.z);
    o.z = bf16x2(v1.y, v1.x);
    o.w = bf16x2(v1.w, v1.z);
    *reinterpret_cast<uint4*>(dst + (size_t)j * 8) = o;
}

// ---------------------------------------------------------------------------
// Projection: Out[c][n] for c = h*64+y.  Out = g . W^T.
// CTA tile 64n x 64c, 128 threads (4 warps: 2m x 2n, warp tile 32x32).
// 3-stage cp.async pipeline, one __syncthreads per k-chunk.
// grid (12, 32, 2) = 768 CTAs -> ~5 resident CTAs/SM (latency hiding).
// Dynamic smem: 3 * 10240 = 30720 B.
// ---------------------------------------------------------------------------
#define PROWB 80
#define PA_TILE (64 * PROWB)                // 5120 B
#define PB_TILE (64 * PROWB)                // 5120 B
#define P_STAGE (PA_TILE + PB_TILE)         // 10240 B
#define P_SMEM (3 * P_STAGE)                // 30720 B

__global__ void __launch_bounds__(128) proj_kernel()
{
    extern __shared__ char sm[];
    const uint32_t sb = smem_u32(sm);
    const int tid = threadIdx.x, lane = tid & 31, wid = tid >> 5;
    const int wm = wid & 1, wn = wid >> 1;
    const int c0 = blockIdx.x * 64, n0 = blockIdx.y * 64;
    const __nv_bfloat16* __restrict__ A = g_gb;
    const __nv_bfloat16* __restrict__ B = blockIdx.z ? g_Wkb : g_Wqb;
    __nv_bfloat16* __restrict__ Out = blockIdx.z ? g_K : g_Q;
    const float scale = blockIdx.z ? 1.0f : 0.125f;

    auto load_chunk = [&](int ch, int st) {
        const int d0 = ch * 32;
        const uint32_t abuf = sb + st * P_STAGE;
        const uint32_t bbuf = abuf + PA_TILE;
        // A: 64 rows x 4 granules(16B) = 256 -> 2 per thread
        #pragma unroll
        for (int i = 0; i < 2; i++) {
            int gi = tid + i * 128;
            int r = gi >> 2, c = gi & 3;
            cpa16(abuf + r * PROWB + c * 16, A + (size_t)(n0 + r) * DD + d0 + c * 8);
        }
        // B: 64 rows x 4 granules = 256 -> 2 per thread
        #pragma unroll
        for (int i = 0; i < 2; i++) {
            int gi = tid + i * 128;
            int r = gi >> 2, c = gi & 3;
            cpa16(bbuf + r * PROWB + c * 16, B + (size_t)(c0 + r) * DD + d0 + c * 8);
        }
    };

    float acc[2][4][4];
    #pragma unroll
    for (int mt = 0; mt < 2; mt++)
        #pragma unroll
        for (int nt = 0; nt < 4; nt++)
            #pragma unroll
            for (int k = 0; k < 4; k++) acc[mt][nt][k] = 0.f;

    const int lr = lane & 7;
    const uint32_t aoff = (uint32_t)((wm * 32 + lr + ((lane >> 3) & 1) * 8) * PROWB
                                     + ((lane >> 4) & 1) * 16);
    const uint32_t boff = (uint32_t)((wn * 32 + lr + ((lane >> 4) & 1) * 8) * PROWB
                                     + ((lane >> 3) & 1) * 16);

    load_chunk(0, 0); CP_COMMIT();
    load_chunk(1, 1); CP_COMMIT();

    int rst = 0, wst = 2;
    for (int ch = 0; ch < 24; ch++) {
        if (ch < 23) CP_WAIT(1); else CP_WAIT(0);
        __syncthreads();

        const uint32_t stage = sb + rst * P_STAGE;
        const uint32_t abase = stage + aoff;
        const uint32_t bbase = stage + PA_TILE + boff;
        #pragma unroll
        for (int ks = 0; ks < 2; ks++) {
            uint32_t a0[4], a1[4];
            ldsm4(a0[0], a0[1], a0[2], a0[3], abase + ks * 32);
            ldsm4(a1[0], a1[1], a1[2], a1[3], abase + 16 * PROWB + ks * 32);
            #pragma unroll
            for (int ntp = 0; ntp < 2; ntp++) {
                uint32_t b0, b1, b2, b3;
                ldsm4(b0, b1, b2, b3, bbase + ntp * 16 * PROWB + ks * 32);
                mma16816(acc[0][2 * ntp],     a0, b0, b1);
                mma16816(acc[1][2 * ntp],     a1, b0, b1);
                mma16816(acc[0][2 * ntp + 1], a0, b2, b3);
                mma16816(acc[1][2 * ntp + 1], a1, b2, b3);
            }
        }
        if (ch < 22) { load_chunk(ch + 2, wst); CP_COMMIT(); }
        rst = (rst == 2) ? 0 : rst + 1;
        wst = (wst == 2) ? 0 : wst + 1;
    }

    const int cw = c0 + wn * 32;
    const int h = cw >> 6;
    const int y0 = cw & 63;
    const int rbase = n0 + wm * 32 + (lane >> 2);
    #pragma unroll
    for (int mt = 0; mt < 2; mt++) {
        #pragma unroll
        for (int nt = 0; nt < 4; nt++) {
            const int y = y0 + nt * 8 + (lane & 3) * 2;
            const int n1 = rbase + mt * 16;
            uint32_t p0 = bf16x2(acc[mt][nt][1] * scale, acc[mt][nt][0] * scale);
            uint32_t p1 = bf16x2(acc[mt][nt][3] * scale, acc[mt][nt][2] * scale);
            *reinterpret_cast<uint32_t*>(&Out[((size_t)h * NN + n1) * YY + y])     = p0;
            *reinterpret_cast<uint32_t*>(&Out[((size_t)h * NN + n1 + 8) * YY + y]) = p1;
        }
    }
}

// ---------------------------------------------------------------------------
// Fused scores + LSE, split-K (KSPLIT=2). CTA per (qtile 64, head, K-half).
// 4 warps x 16 q-rows, 8 K-chunks per CTA. Flattened branchless-triggered
// online LSE. grid (32, 12, 2) = 768 CTAs of 128 threads.  (R13 version)
// ---------------------------------------------------------------------------
#define ROWB 144
#define S_TILE (128 * ROWB)                 // 18432 B
#define S_RED  (2 * S_TILE)
#define S_SMEM (S_RED + 128 * 4)            // 37376 B

__global__ void __launch_bounds__(128) scores_kernel(float* __restrict__ out)
{
    extern __shared__ char sm[];
    const uint32_t sb = smem_u32(sm);
    const int tid = threadIdx.x, lane = tid & 31, wid = tid >> 5;
    const int h = blockIdx.y, qt = blockIdx.x, half = blockIdx.z;
    const int grp = h * NQT + qt;

    const __nv_bfloat16* __restrict__ Qsrc = g_Q + ((size_t)h * NN + qt * 64) * YY;
    const __nv_bfloat16* __restrict__ Ksrc = g_K + (size_t)h * NN * YY
                                           + (size_t)half * (NN / KSPLIT) * YY;

    auto load_q = [&]() {
        #pragma unroll
        for (int i = 0; i < 4; i++) {
            int gi = tid + i * 128;
            int r = gi >> 3, c = gi & 7;
            cpa16(sb + r * ROWB + c * 16, Qsrc + (size_t)r * YY + c * 8);
        }
    };
    auto load_k = [&](int ch) {
        const int k0 = ch * 128;
        const uint32_t buf = sb + (ch & 1) * S_TILE;
        #pragma unroll
        for (int i = 0; i < 8; i++) {
            int gi = tid + i * 128;
            int r = gi >> 3, c = gi & 7;
            cpa16(buf + r * ROWB + c * 16, Ksrc + (size_t)(k0 + r) * YY + c * 8);
        }
    };

    const int lr = lane & 7;
    const uint32_t aoff = (uint32_t)((wid * 16 + lr + ((lane >> 3) & 1) * 8) * ROWB
                                     + ((lane >> 4) & 1) * 16);
    const uint32_t boff = (uint32_t)((lr + ((lane >> 4) & 1) * 8) * ROWB
                                     + ((lane >> 3) & 1) * 16);

    // Stage Q through buffer 0, pull fragments into registers, then free it.
    load_q(); CP_COMMIT(); CP_WAIT(0);
    __syncthreads();
    uint32_t aR[4][4];
    #pragma unroll
    for (int ks = 0; ks < 4; ks++)
        ldsm4(aR[ks][0], aR[ks][1], aR[ks][2], aR[ks][3], sb + aoff + ks * 32);
    __syncthreads();

    load_k(0); CP_COMMIT();

    float m0 = -INFINITY, l0 = 0.f;   // row a = wid*16 + (lane>>2)
    float m1 = -INFINITY, l1 = 0.f;   // row b = row a + 8

    for (int ch = 0; ch < KCH; ch++) {
        if (ch < KCH - 1) { load_k(ch + 1); CP_COMMIT(); CP_WAIT(1); }
        else CP_WAIT(0);
        __syncthreads();

        const uint32_t bbase = sb + (ch & 1) * S_TILE + boff;
        #pragma unroll
        for (int ntp = 0; ntp < 8; ntp++) {
            float acc[8];
            #pragma unroll
            for (int j = 0; j < 8; j++) acc[j] = 0.f;
            #pragma unroll
            for (int ks = 0; ks < 4; ks++) {
                uint32_t b0, b1, b2, b3;
                ldsm4(b0, b1, b2, b3, bbase + ntp * 16 * ROWB + ks * 32);
                mma16816(acc,     aR[ks], b0, b1);
                mma16816(acc + 4, aR[ks], b2, b3);
            }
            // rows: acc[0],[1],[4],[5] -> row a ; acc[2],[3],[6],[7] -> row b
            float ca = fmaxf(fmaxf(acc[0], acc[1]), fmaxf(acc[4], acc[5]));
            float cb = fmaxf(fmaxf(acc[2], acc[3]), fmaxf(acc[6], acc[7]));
            if (ca > m0 - 16.0f) {        // flat triggered path, no inner branches
                float mn = fmaxf(m0, ca);
                l0 = l0 * __expf(m0 - mn)
                   + __expf(acc[0] - mn) + __expf(acc[1] - mn)
                   + __expf(acc[4] - mn) + __expf(acc[5] - mn);
                m0 = mn;
            }
            if (cb > m1 - 16.0f) {
                float mn = fmaxf(m1, cb);
                l1 = l1 * __expf(m1 - mn)
                   + __expf(acc[2] - mn) + __expf(acc[3] - mn)
                   + __expf(acc[6] - mn) + __expf(acc[7] - mn);
                m1 = mn;
            }
        }
        __syncthreads();
    }

    // combine the 4 lanes of each quad-row (same row, disjoint k-cols)
    #pragma unroll
    for (int off = 1; off <= 2; off <<= 1) {
        float mo = __shfl_xor_sync(0xffffffffu, m0, off);
        float lo = __shfl_xor_sync(0xffffffffu, l0, off);
        float mm = fmaxf(m0, mo);
        l0 = l0 * __expf(m0 - mm) + lo * __expf(mo - mm);
        m0 = mm;
        mo = __shfl_xor_sync(0xffffffffu, m1, off);
        lo = __shfl_xor_sync(0xffffffffu, l1, off);
        mm = fmaxf(m1, mo);
        l1 = l1 * __expf(m1 - mm) + lo * __expf(mo - mm);
        m1 = mm;
    }

    // publish per-row (m,l) for this half
    float2* gml = g_ml + (size_t)grp * (KSPLIT * 64) + half * 64;
    if ((lane & 3) == 0) {
        int row = wid * 16 + (lane >> 2);
        gml[row]     = make_float2(m0, l0);
        gml[row + 8] = make_float2(m1, l1);
    }
    __threadfence();
    __syncthreads();

    __shared__ unsigned int pos;
    if (tid == 0) pos = atomicAdd(&g_ticket2[grp], 1u);
    __syncthreads();
    if (pos != KSPLIT - 1) return;

    // second finisher: merge halves (deterministic), row LSE, group sum
    float* red = reinterpret_cast<float*>(sm + S_RED);
    {
        float A = 0.f;
        if (tid < 64) {
            const float2* base = g_ml + (size_t)grp * (KSPLIT * 64);
            float2 a = __ldcg(&base[tid]);
            float2 b = __ldcg(&base[64 + tid]);
            float mm = fmaxf(a.x, b.x);
            float L = a.y * __expf(a.x - mm) + b.y * __expf(b.x - mm);
            A = mm + logf(L);
        }
        red[tid] = A;
        __syncthreads();
        if (tid < 32) {
            float s = red[tid] + red[tid + 32];
            #pragma unroll
            for (int off = 16; off > 0; off >>= 1)
                s += __shfl_xor_sync(0xffffffffu, s, off);
            if (tid == 0) g_partial[grp] = s;
        }
    }

    // global last-group election -> final deterministic sum of 384 partials
    __shared__ unsigned int is_last;
    __threadfence();
    if (tid == 0) is_last = (atomicAdd(&g_ticket, 1u) == NGRP - 1);
    __syncthreads();
    if (is_last) {
        __threadfence();
        float s = __ldcg(&g_partial[tid]) + __ldcg(&g_partial[tid + 128])
                + __ldcg(&g_partial[tid + 256]);
        red[tid] = s;
        __syncthreads();
        if (tid < 32) {
            float t = red[tid] + red[tid + 32] + red[tid + 64] + red[tid + 96];
            #pragma unroll
            for (int off = 16; off > 0; off >>= 1)
                t += __shfl_xor_sync(0xffffffffu, t, off);
            if (tid == 0) out[0] = -8.0f * t;
        }
    }
}

extern "C" void kernel_launch(void* const* d_in, const int* in_sizes, int n_in,
                              void* d_out, int out_size)
{
    (void)in_sizes; (void)n_in; (void)out_size;
    const float* g  = (const float*)d_in[0];
    const float* Wq = (const float*)d_in[1];
    const float* Wk = (const float*)d_in[2];
    float* out = (float*)d_out;

    const int convN = NG8 + 2 * NW8;
    conv_kernel<<<(convN + 255) / 256, 256>>>(g, Wq, Wk);
    proj_kernel<<<dim3(12, 32, 2), 128, P_SMEM>>>();
    scores_kernel<<<dim3(NQT, HH, KSPLIT), 128, S_SMEM>>>(out);
}

// round 16
// speedup vs baseline: 1.0309x; 1.0309x over previous
#include <cuda_runtime.h>
#include <cuda_bf16.h>
#include <cstdint>
#include <math.h>

#define NN 2048
#define DD 768
#define HH 12
#define YY 64

#define NQT 32                 // q-tiles per head (qtile = 64 rows)
#define NGRP (HH * NQT)        // 384 (h, qt) groups
#define KSPLIT 2               // K-range halves per group
#define KCH (NN / KSPLIT / 128)// 8 chunks of 128 per CTA

// ---------------------------------------------------------------------------
// Scratch (__device__ globals; no allocation allowed)
// ---------------------------------------------------------------------------
__device__ __nv_bfloat16 g_gb [NN * DD];       // g in bf16
__device__ __nv_bfloat16 g_Wqb[HH * YY * DD];  // Wq in bf16
__device__ __nv_bfloat16 g_Wkb[HH * YY * DD];  // Wk in bf16
__device__ __nv_bfloat16 g_Q[HH * NN * YY];    // [h][n][y], pre-scaled by beta
__device__ __nv_bfloat16 g_K[HH * NN * YY];    // [h][n][y]
__device__ float2 g_ml[NGRP * KSPLIT * 64];    // per-row (m,l) per half
__device__ float g_partial[NGRP];              // per-group LSE row sums
__device__ unsigned int g_ticket2[NGRP];       // per-group pair election
__device__ unsigned int g_ticket;              // global last-group election

// ---------------------------------------------------------------------------
// Helpers (standard sm_80+ features: ldmatrix / mma.sync / cp.async)
// ---------------------------------------------------------------------------
__device__ __forceinline__ uint32_t smem_u32(const void* p) {
    uint32_t a;
    asm("{ .reg .u64 t; cvta.to.shared.u64 t, %1; cvt.u32.u64 %0, t; }" : "=r"(a) : "l"(p));
    return a;
}

__device__ __forceinline__ void cpa16(uint32_t dst, const void* src) {
    asm volatile("cp.async.cg.shared.global [%0], [%1], 16;" :: "r"(dst), "l"(src));
}
#define CP_COMMIT() asm volatile("cp.async.commit_group;" ::: "memory")
#define CP_WAIT(n)  asm volatile("cp.async.wait_group %0;" :: "n"(n) : "memory")

__device__ __forceinline__ void ldsm4(uint32_t& r0, uint32_t& r1, uint32_t& r2, uint32_t& r3,
                                      uint32_t addr) {
    asm volatile("ldmatrix.sync.aligned.m8n8.x4.shared.b16 {%0,%1,%2,%3}, [%4];"
                 : "=r"(r0), "=r"(r1), "=r"(r2), "=r"(r3) : "r"(addr));
}

__device__ __forceinline__ void mma16816(float* c, const uint32_t* a, uint32_t b0, uint32_t b1) {
    asm volatile(
        "mma.sync.aligned.m16n8k16.row.col.f32.bf16.bf16.f32 "
        "{%0,%1,%2,%3}, {%4,%5,%6,%7}, {%8,%9}, {%0,%1,%2,%3};"
        : "+f"(c[0]), "+f"(c[1]), "+f"(c[2]), "+f"(c[3])
        : "r"(a[0]), "r"(a[1]), "r"(a[2]), "r"(a[3]), "r"(b0), "r"(b1));
}

// D = A*B + 0 : separate D/C form with a zero C-quad; avoids acc zero-init MOVs
__device__ __forceinline__ void mma16816_z(float* d, const uint32_t* a, uint32_t b0, uint32_t b1) {
    asm volatile(
        "mma.sync.aligned.m16n8k16.row.col.f32.bf16.bf16.f32 "
        "{%0,%1,%2,%3}, {%4,%5,%6,%7}, {%8,%9}, {%10,%11,%12,%13};"
        : "=f"(d[0]), "=f"(d[1]), "=f"(d[2]), "=f"(d[3])
        : "r"(a[0]), "r"(a[1]), "r"(a[2]), "r"(a[3]), "r"(b0), "r"(b1),
          "f"(0.0f), "f"(0.0f), "f"(0.0f), "f"(0.0f));
}

__device__ __forceinline__ uint32_t bf16x2(float hi, float lo) {
    uint32_t r;
    asm("cvt.rn.bf16x2.f32 %0, %1, %2;" : "=r"(r) : "f"(hi), "f"(lo));
    return r;
}

// ---------------------------------------------------------------------------
// Convert f32 inputs -> bf16 globals; reset tickets. (R8 version: max TLP)
// ---------------------------------------------------------------------------
#define NG8 (NN * DD / 8)          // 196608
#define NW8 (HH * YY * DD / 8)     // 73728

__global__ void __launch_bounds__(256) conv_kernel(const float* __restrict__ g,
                                                   const float* __restrict__ wq,
                                                   const float* __restrict__ wk)
{
    int i = blockIdx.x * 256 + threadIdx.x;
    if (i == 0) g_ticket = 0;
    if (i < NGRP) g_ticket2[i] = 0;
    const float* src;
    __nv_bfloat16* dst;
    int j;
    if (i < NG8)                { src = g;  dst = g_gb;  j = i; }
    else if (i < NG8 + NW8)     { src = wq; dst = g_Wqb; j = i - NG8; }
    else if (i < NG8 + 2 * NW8) { src = wk; dst = g_Wkb; j = i - NG8 - NW8; }
    else return;
    float4 v0 = *reinterpret_cast<const float4*>(src + (size_t)j * 8);
    float4 v1 = *reinterpret_cast<const float4*>(src + (size_t)j * 8 + 4);
    uint4 o;
    o.x = bf16x2(v0.y, v0.x);
    o.y = bf16x2(v0.w, v0.z);
    o.z = bf16x2(v1.y, v1.x);
    o.w = bf16x2(v1.w, v1.z);
    *reinterpret_cast<uint4*>(dst + (size_t)j * 8) = o;
}

// ---------------------------------------------------------------------------
// Projection: Out[c][n] for c = h*64+y.  Out = g . W^T.   (R14 version)
// CTA tile 64n x 128c, 128 threads (4 warps: 2m x 2n, warp tile 32x64).
// 3-stage cp.async pipeline, one __syncthreads per k-chunk.
// grid (6, 32, 2) = 384 CTAs. Dynamic smem: 3*15360 = 46080 B.
// ---------------------------------------------------------------------------
#define PROWB 80
#define PA_TILE (64 * PROWB)                // 5120 B
#define PB_TILE (128 * PROWB)               // 10240 B
#define P_STAGE (PA_TILE + PB_TILE)         // 15360 B
#define P_SMEM (3 * P_STAGE)                // 46080 B

__global__ void __launch_bounds__(128) proj_kernel()
{
    extern __shared__ char sm[];
    const uint32_t sb = smem_u32(sm);
    const int tid = threadIdx.x, lane = tid & 31, wid = tid >> 5;
    const int wm = wid & 1, wn = wid >> 1;
    const int c0 = blockIdx.x * 128, n0 = blockIdx.y * 64;
    const __nv_bfloat16* __restrict__ A = g_gb;
    const __nv_bfloat16* __restrict__ B = blockIdx.z ? g_Wkb : g_Wqb;
    __nv_bfloat16* __restrict__ Out = blockIdx.z ? g_K : g_Q;
    const float scale = blockIdx.z ? 1.0f : 0.125f;

    auto load_chunk = [&](int ch, int st) {
        const int d0 = ch * 32;
        const uint32_t abuf = sb + st * P_STAGE;
        const uint32_t bbuf = abuf + PA_TILE;
        #pragma unroll
        for (int i = 0; i < 2; i++) {
            int gi = tid + i * 128;
            int r = gi >> 2, c = gi & 3;
            cpa16(abuf + r * PROWB + c * 16, A + (size_t)(n0 + r) * DD + d0 + c * 8);
        }
        #pragma unroll
        for (int i = 0; i < 4; i++) {
            int gi = tid + i * 128;
            int r = gi >> 2, c = gi & 3;
            cpa16(bbuf + r * PROWB + c * 16, B + (size_t)(c0 + r) * DD + d0 + c * 8);
        }
    };

    float acc[2][8][4];
    #pragma unroll
    for (int mt = 0; mt < 2; mt++)
        #pragma unroll
        for (int nt = 0; nt < 8; nt++)
            #pragma unroll
            for (int k = 0; k < 4; k++) acc[mt][nt][k] = 0.f;

    const int lr = lane & 7;
    const uint32_t aoff = (uint32_t)((wm * 32 + lr + ((lane >> 3) & 1) * 8) * PROWB
                                     + ((lane >> 4) & 1) * 16);
    const uint32_t boff = (uint32_t)((wn * 64 + lr + ((lane >> 4) & 1) * 8) * PROWB
                                     + ((lane >> 3) & 1) * 16);

    load_chunk(0, 0); CP_COMMIT();
    load_chunk(1, 1); CP_COMMIT();

    int rst = 0, wst = 2;
    for (int ch = 0; ch < 24; ch++) {
        if (ch < 23) CP_WAIT(1); else CP_WAIT(0);
        __syncthreads();

        const uint32_t stage = sb + rst * P_STAGE;
        const uint32_t abase = stage + aoff;
        const uint32_t bbase = stage + PA_TILE + boff;
        #pragma unroll
        for (int ks = 0; ks < 2; ks++) {
            uint32_t a0[4], a1[4];
            ldsm4(a0[0], a0[1], a0[2], a0[3], abase + ks * 32);
            ldsm4(a1[0], a1[1], a1[2], a1[3], abase + 16 * PROWB + ks * 32);
            #pragma unroll
            for (int ntp = 0; ntp < 4; ntp++) {
                uint32_t b0, b1, b2, b3;
                ldsm4(b0, b1, b2, b3, bbase + ntp * 16 * PROWB + ks * 32);
                mma16816(acc[0][2 * ntp],     a0, b0, b1);
                mma16816(acc[1][2 * ntp],     a1, b0, b1);
                mma16816(acc[0][2 * ntp + 1], a0, b2, b3);
                mma16816(acc[1][2 * ntp + 1], a1, b2, b3);
            }
        }
        if (ch < 22) { load_chunk(ch + 2, wst); CP_COMMIT(); }
        rst = (rst == 2) ? 0 : rst + 1;
        wst = (wst == 2) ? 0 : wst + 1;
    }

    const int h = (c0 >> 6) + wn;
    const int rbase = n0 + wm * 32 + (lane >> 2);
    #pragma unroll
    for (int mt = 0; mt < 2; mt++) {
        #pragma unroll
        for (int nt = 0; nt < 8; nt++) {
            const int y = nt * 8 + (lane & 3) * 2;
            const int n1 = rbase + mt * 16;
            uint32_t p0 = bf16x2(acc[mt][nt][1] * scale, acc[mt][nt][0] * scale);
            uint32_t p1 = bf16x2(acc[mt][nt][3] * scale, acc[mt][nt][2] * scale);
            *reinterpret_cast<uint32_t*>(&Out[((size_t)h * NN + n1) * YY + y])     = p0;
            *reinterpret_cast<uint32_t*>(&Out[((size_t)h * NN + n1 + 8) * YY + y]) = p1;
        }
    }
}

// ---------------------------------------------------------------------------
// Fused scores + LSE, split-K (KSPLIT=2). CTA per (qtile 64, head, K-half).
// 4 warps x 16 q-rows, 8 K-chunks per CTA. Flattened branchless-triggered
// online LSE; first k-step uses D=A*B+0 MMA (no acc zero-init MOVs).
// grid (32, 12, 2) = 768 CTAs of 128 threads.
// ---------------------------------------------------------------------------
#define ROWB 144
#define S_TILE (128 * ROWB)                 // 18432 B
#define S_RED  (2 * S_TILE)
#define S_SMEM (S_RED + 128 * 4)            // 37376 B

__global__ void __launch_bounds__(128) scores_kernel(float* __restrict__ out)
{
    extern __shared__ char sm[];
    const uint32_t sb = smem_u32(sm);
    const int tid = threadIdx.x, lane = tid & 31, wid = tid >> 5;
    const int h = blockIdx.y, qt = blockIdx.x, half = blockIdx.z;
    const int grp = h * NQT + qt;

    const __nv_bfloat16* __restrict__ Qsrc = g_Q + ((size_t)h * NN + qt * 64) * YY;
    const __nv_bfloat16* __restrict__ Ksrc = g_K + (size_t)h * NN * YY
                                           + (size_t)half * (NN / KSPLIT) * YY;

    auto load_q = [&]() {
        #pragma unroll
        for (int i = 0; i < 4; i++) {
            int gi = tid + i * 128;
            int r = gi >> 3, c = gi & 7;
            cpa16(sb + r * ROWB + c * 16, Qsrc + (size_t)r * YY + c * 8);
        }
    };
    auto load_k = [&](int ch) {
        const int k0 = ch * 128;
        const uint32_t buf = sb + (ch & 1) * S_TILE;
        #pragma unroll
        for (int i = 0; i < 8; i++) {
            int gi = tid + i * 128;
            int r = gi >> 3, c = gi & 7;
            cpa16(buf + r * ROWB + c * 16, Ksrc + (size_t)(k0 + r) * YY + c * 8);
        }
    };

    const int lr = lane & 7;
    const uint32_t aoff = (uint32_t)((wid * 16 + lr + ((lane >> 3) & 1) * 8) * ROWB
                                     + ((lane >> 4) & 1) * 16);
    const uint32_t boff = (uint32_t)((lr + ((lane >> 4) & 1) * 8) * ROWB
                                     + ((lane >> 3) & 1) * 16);

    // Stage Q through buffer 0, pull fragments into registers, then free it.
    load_q(); CP_COMMIT(); CP_WAIT(0);
    __syncthreads();
    uint32_t aR[4][4];
    #pragma unroll
    for (int ks = 0; ks < 4; ks++)
        ldsm4(aR[ks][0], aR[ks][1], aR[ks][2], aR[ks][3], sb + aoff + ks * 32);
    __syncthreads();

    load_k(0); CP_COMMIT();

    float m0 = -INFINITY, l0 = 0.f;   // row a = wid*16 + (lane>>2)
    float m1 = -INFINITY, l1 = 0.f;   // row b = row a + 8

    for (int ch = 0; ch < KCH; ch++) {
        if (ch < KCH - 1) { load_k(ch + 1); CP_COMMIT(); CP_WAIT(1); }
        else CP_WAIT(0);
        __syncthreads();

        const uint32_t bbase = sb + (ch & 1) * S_TILE + boff;
        #pragma unroll
        for (int ntp = 0; ntp < 8; ntp++) {
            float acc[8];
            #pragma unroll
            for (int ks = 0; ks < 4; ks++) {
                uint32_t b0, b1, b2, b3;
                ldsm4(b0, b1, b2, b3, bbase + ntp * 16 * ROWB + ks * 32);
                if (ks == 0) {
                    mma16816_z(acc,     aR[ks], b0, b1);
                    mma16816_z(acc + 4, aR[ks], b2, b3);
                } else {
                    mma16816(acc,     aR[ks], b0, b1);
                    mma16816(acc + 4, aR[ks], b2, b3);
                }
            }
            // rows: acc[0],[1],[4],[5] -> row a ; acc[2],[3],[6],[7] -> row b
            float ca = fmaxf(fmaxf(acc[0], acc[1]), fmaxf(acc[4], acc[5]));
            float cb = fmaxf(fmaxf(acc[2], acc[3]), fmaxf(acc[6], acc[7]));
            if (ca > m0 - 16.0f) {        // flat triggered path, no inner branches
                float mn = fmaxf(m0, ca);
                l0 = l0 * __expf(m0 - mn)
                   + __expf(acc[0] - mn) + __expf(acc[1] - mn)
                   + __expf(acc[4] - mn) + __expf(acc[5] - mn);
                m0 = mn;
            }
            if (cb > m1 - 16.0f) {
                float mn = fmaxf(m1, cb);
                l1 = l1 * __expf(m1 - mn)
                   + __expf(acc[2] - mn) + __expf(acc[3] - mn)
                   + __expf(acc[6] - mn) + __expf(acc[7] - mn);
                m1 = mn;
            }
        }
        __syncthreads();
    }

    // combine the 4 lanes of each quad-row (same row, disjoint k-cols)
    #pragma unroll
    for (int off = 1; off <= 2; off <<= 1) {
        float mo = __shfl_xor_sync(0xffffffffu, m0, off);
        float lo = __shfl_xor_sync(0xffffffffu, l0, off);
        float mm = fmaxf(m0, mo);
        l0 = l0 * __expf(m0 - mm) + lo * __expf(mo - mm);
        m0 = mm;
        mo = __shfl_xor_sync(0xffffffffu, m1, off);
        lo = __shfl_xor_sync(0xffffffffu, l1, off);
        mm = fmaxf(m1, mo);
        l1 = l1 * __expf(m1 - mm) + lo * __expf(mo - mm);
        m1 = mm;
    }

    // publish per-row (m,l) for this half
    float2* gml = g_ml + (size_t)grp * (KSPLIT * 64) + half * 64;
    if ((lane & 3) == 0) {
        int row = wid * 16 + (lane >> 2);
        gml[row]     = make_float2(m0, l0);
        gml[row + 8] = make_float2(m1, l1);
    }
    __threadfence();
    __syncthreads();

    __shared__ unsigned int pos;
    if (tid == 0) pos = atomicAdd(&g_ticket2[grp], 1u);
    __syncthreads();
    if (pos != KSPLIT - 1) return;

    // second finisher: merge halves (deterministic), row LSE, group sum
    float* red = reinterpret_cast<float*>(sm + S_RED);
    {
        float A = 0.f;
        if (tid < 64) {
            const float2* base = g_ml + (size_t)grp * (KSPLIT * 64);
            float2 a = __ldcg(&base[tid]);
            float2 b = __ldcg(&base[64 + tid]);
            float mm = fmaxf(a.x, b.x);
            float L = a.y * __expf(a.x - mm) + b.y * __expf(b.x - mm);
            A = mm + logf(L);
        }
        red[tid] = A;
        __syncthreads();
        if (tid < 32) {
            float s = red[tid] + red[tid + 32];
            #pragma unroll
            for (int off = 16; off > 0; off >>= 1)
                s += __shfl_xor_sync(0xffffffffu, s, off);
            if (tid == 0) g_partial[grp] = s;
        }
    }

    // global last-group election -> final deterministic sum of 384 partials
    __shared__ unsigned int is_last;
    __threadfence();
    if (tid == 0) is_last = (atomicAdd(&g_ticket, 1u) == NGRP - 1);
    __syncthreads();
    if (is_last) {
        __threadfence();
        float s = __ldcg(&g_partial[tid]) + __ldcg(&g_partial[tid + 128])
                + __ldcg(&g_partial[tid + 256]);
        red[tid] = s;
        __syncthreads();
        if (tid < 32) {
            float t = red[tid] + red[tid + 32] + red[tid + 64] + red[tid + 96];
            #pragma unroll
            for (int off = 16; off > 0; off >>= 1)
                t += __shfl_xor_sync(0xffffffffu, t, off);
            if (tid == 0) out[0] = -8.0f * t;
        }
    }
}

extern "C" void kernel_launch(void* const* d_in, const int* in_sizes, int n_in,
                              void* d_out, int out_size)
{
    (void)in_sizes; (void)n_in; (void)out_size;
    const float* g  = (const float*)d_in[0];
    const float* Wq = (const float*)d_in[1];
    const float* Wk = (const float*)d_in[2];
    float* out = (float*)d_out;

    const int convN = NG8 + 2 * NW8;
    conv_kernel<<<(convN + 255) / 256, 256>>>(g, Wq, Wk);
    proj_kernel<<<dim3(6, 32, 2), 128, P_SMEM>>>();
    scores_kernel<<<dim3(NQT, HH, KSPLIT), 128, S_SMEM>>>(out);
}

// round 17
// speedup vs baseline: 1.0354x; 1.0044x over previous
#include <cuda_runtime.h>
#include <cuda_bf16.h>
#include <cstdint>
#include <math.h>

#define NN 2048
#define DD 768
#define HH 12
#define YY 64

#define NQT 32                 // q-tiles per head (qtile = 64 rows)
#define NGRP (HH * NQT)        // 384 (h, qt) groups
#define KSPLIT 2               // K-range halves per group
#define KROWS 64               // K-chunk rows (was 128)
#define KCH (NN / KSPLIT / KROWS) // 16 chunks per CTA

// ---------------------------------------------------------------------------
// Scratch (__device__ globals; no allocation allowed)
// ---------------------------------------------------------------------------
__device__ __nv_bfloat16 g_gb [NN * DD];       // g in bf16
__device__ __nv_bfloat16 g_Wqb[HH * YY * DD];  // Wq in bf16
__device__ __nv_bfloat16 g_Wkb[HH * YY * DD];  // Wk in bf16
__device__ __nv_bfloat16 g_Q[HH * NN * YY];    // [h][n][y], pre-scaled by beta
__device__ __nv_bfloat16 g_K[HH * NN * YY];    // [h][n][y]
__device__ float2 g_ml[NGRP * KSPLIT * 64];    // per-row (m,l) per half
__device__ float g_partial[NGRP];              // per-group LSE row sums
__device__ unsigned int g_ticket2[NGRP];       // per-group pair election
__device__ unsigned int g_ticket;              // global last-group election

// ---------------------------------------------------------------------------
// Helpers (standard sm_80+ features: ldmatrix / mma.sync / cp.async)
// ---------------------------------------------------------------------------
__device__ __forceinline__ uint32_t smem_u32(const void* p) {
    uint32_t a;
    asm("{ .reg .u64 t; cvta.to.shared.u64 t, %1; cvt.u32.u64 %0, t; }" : "=r"(a) : "l"(p));
    return a;
}

__device__ __forceinline__ void cpa16(uint32_t dst, const void* src) {
    asm volatile("cp.async.cg.shared.global [%0], [%1], 16;" :: "r"(dst), "l"(src));
}
#define CP_COMMIT() asm volatile("cp.async.commit_group;" ::: "memory")
#define CP_WAIT(n)  asm volatile("cp.async.wait_group %0;" :: "n"(n) : "memory")

__device__ __forceinline__ void ldsm4(uint32_t& r0, uint32_t& r1, uint32_t& r2, uint32_t& r3,
                                      uint32_t addr) {
    asm volatile("ldmatrix.sync.aligned.m8n8.x4.shared.b16 {%0,%1,%2,%3}, [%4];"
                 : "=r"(r0), "=r"(r1), "=r"(r2), "=r"(r3) : "r"(addr));
}

__device__ __forceinline__ void mma16816(float* c, const uint32_t* a, uint32_t b0, uint32_t b1) {
    asm volatile(
        "mma.sync.aligned.m16n8k16.row.col.f32.bf16.bf16.f32 "
        "{%0,%1,%2,%3}, {%4,%5,%6,%7}, {%8,%9}, {%0,%1,%2,%3};"
        : "+f"(c[0]), "+f"(c[1]), "+f"(c[2]), "+f"(c[3])
        : "r"(a[0]), "r"(a[1]), "r"(a[2]), "r"(a[3]), "r"(b0), "r"(b1));
}

// D = A*B + 0 : separate D/C form with a zero C-quad; avoids acc zero-init MOVs
__device__ __forceinline__ void mma16816_z(float* d, const uint32_t* a, uint32_t b0, uint32_t b1) {
    asm volatile(
        "mma.sync.aligned.m16n8k16.row.col.f32.bf16.bf16.f32 "
        "{%0,%1,%2,%3}, {%4,%5,%6,%7}, {%8,%9}, {%10,%11,%12,%13};"
        : "=f"(d[0]), "=f"(d[1]), "=f"(d[2]), "=f"(d[3])
        : "r"(a[0]), "r"(a[1]), "r"(a[2]), "r"(a[3]), "r"(b0), "r"(b1),
          "f"(0.0f), "f"(0.0f), "f"(0.0f), "f"(0.0f));
}

__device__ __forceinline__ uint32_t bf16x2(float hi, float lo) {
    uint32_t r;
    asm("cvt.rn.bf16x2.f32 %0, %1, %2;" : "=r"(r) : "f"(hi), "f"(lo));
    return r;
}

// ---------------------------------------------------------------------------
// Convert f32 inputs -> bf16 globals; reset tickets. (R8 version: max TLP)
// ---------------------------------------------------------------------------
#define NG8 (NN * DD / 8)          // 196608
#define NW8 (HH * YY * DD / 8)     // 73728

__global__ void __launch_bounds__(256) conv_kernel(const float* __restrict__ g,
                                                   const float* __restrict__ wq,
                                                   const float* __restrict__ wk)
{
    int i = blockIdx.x * 256 + threadIdx.x;
    if (i == 0) g_ticket = 0;
    if (i < NGRP) g_ticket2[i] = 0;
    const float* src;
    __nv_bfloat16* dst;
    int j;
    if (i < NG8)                { src = g;  dst = g_gb;  j = i; }
    else if (i < NG8 + NW8)     { src = wq; dst = g_Wqb; j = i - NG8; }
    else if (i < NG8 + 2 * NW8) { src = wk; dst = g_Wkb; j = i - NG8 - NW8; }
    else return;
    float4 v0 = *reinterpret_cast<const float4*>(src + (size_t)j * 8);
    float4 v1 = *reinterpret_cast<const float4*>(src + (size_t)j * 8 + 4);
    uint4 o;
    o.x = bf16x2(v0.y, v0.x);
    o.y = bf16x2(v0.w, v0.z);
    o.z = bf16x2(v1.y, v1.x);
    o.w = bf16x2(v1.w, v1.z);
    *reinterpret_cast<uint4*>(dst + (size_t)j * 8) = o;
}

// ---------------------------------------------------------------------------
// Projection: Out[c][n] for c = h*64+y.  Out = g . W^T.   (R14/R16 version)
// CTA tile 64n x 128c, 128 threads (4 warps: 2m x 2n, warp tile 32x64).
// 3-stage cp.async pipeline, one __syncthreads per k-chunk.
// grid (6, 32, 2) = 384 CTAs. Dynamic smem: 3*15360 = 46080 B.
// ---------------------------------------------------------------------------
#define PROWB 80
#define PA_TILE (64 * PROWB)                // 5120 B
#define PB_TILE (128 * PROWB)               // 10240 B
#define P_STAGE (PA_TILE + PB_TILE)         // 15360 B
#define P_SMEM (3 * P_STAGE)                // 46080 B

__global__ void __launch_bounds__(128) proj_kernel()
{
    extern __shared__ char sm[];
    const uint32_t sb = smem_u32(sm);
    const int tid = threadIdx.x, lane = tid & 31, wid = tid >> 5;
    const int wm = wid & 1, wn = wid >> 1;
    const int c0 = blockIdx.x * 128, n0 = blockIdx.y * 64;
    const __nv_bfloat16* __restrict__ A = g_gb;
    const __nv_bfloat16* __restrict__ B = blockIdx.z ? g_Wkb : g_Wqb;
    __nv_bfloat16* __restrict__ Out = blockIdx.z ? g_K : g_Q;
    const float scale = blockIdx.z ? 1.0f : 0.125f;

    auto load_chunk = [&](int ch, int st) {
        const int d0 = ch * 32;
        const uint32_t abuf = sb + st * P_STAGE;
        const uint32_t bbuf = abuf + PA_TILE;
        #pragma unroll
        for (int i = 0; i < 2; i++) {
            int gi = tid + i * 128;
            int r = gi >> 2, c = gi & 3;
            cpa16(abuf + r * PROWB + c * 16, A + (size_t)(n0 + r) * DD + d0 + c * 8);
        }
        #pragma unroll
        for (int i = 0; i < 4; i++) {
            int gi = tid + i * 128;
            int r = gi >> 2, c = gi & 3;
            cpa16(bbuf + r * PROWB + c * 16, B + (size_t)(c0 + r) * DD + d0 + c * 8);
        }
    };

    float acc[2][8][4];
    #pragma unroll
    for (int mt = 0; mt < 2; mt++)
        #pragma unroll
        for (int nt = 0; nt < 8; nt++)
            #pragma unroll
            for (int k = 0; k < 4; k++) acc[mt][nt][k] = 0.f;

    const int lr = lane & 7;
    const uint32_t aoff = (uint32_t)((wm * 32 + lr + ((lane >> 3) & 1) * 8) * PROWB
                                     + ((lane >> 4) & 1) * 16);
    const uint32_t boff = (uint32_t)((wn * 64 + lr + ((lane >> 4) & 1) * 8) * PROWB
                                     + ((lane >> 3) & 1) * 16);

    load_chunk(0, 0); CP_COMMIT();
    load_chunk(1, 1); CP_COMMIT();

    int rst = 0, wst = 2;
    for (int ch = 0; ch < 24; ch++) {
        if (ch < 23) CP_WAIT(1); else CP_WAIT(0);
        __syncthreads();

        const uint32_t stage = sb + rst * P_STAGE;
        const uint32_t abase = stage + aoff;
        const uint32_t bbase = stage + PA_TILE + boff;
        #pragma unroll
        for (int ks = 0; ks < 2; ks++) {
            uint32_t a0[4], a1[4];
            ldsm4(a0[0], a0[1], a0[2], a0[3], abase + ks * 32);
            ldsm4(a1[0], a1[1], a1[2], a1[3], abase + 16 * PROWB + ks * 32);
            #pragma unroll
            for (int ntp = 0; ntp < 4; ntp++) {
                uint32_t b0, b1, b2, b3;
                ldsm4(b0, b1, b2, b3, bbase + ntp * 16 * PROWB + ks * 32);
                mma16816(acc[0][2 * ntp],     a0, b0, b1);
                mma16816(acc[1][2 * ntp],     a1, b0, b1);
                mma16816(acc[0][2 * ntp + 1], a0, b2, b3);
                mma16816(acc[1][2 * ntp + 1], a1, b2, b3);
            }
        }
        if (ch < 22) { load_chunk(ch + 2, wst); CP_COMMIT(); }
        rst = (rst == 2) ? 0 : rst + 1;
        wst = (wst == 2) ? 0 : wst + 1;
    }

    const int h = (c0 >> 6) + wn;
    const int rbase = n0 + wm * 32 + (lane >> 2);
    #pragma unroll
    for (int mt = 0; mt < 2; mt++) {
        #pragma unroll
        for (int nt = 0; nt < 8; nt++) {
            const int y = nt * 8 + (lane & 3) * 2;
            const int n1 = rbase + mt * 16;
            uint32_t p0 = bf16x2(acc[mt][nt][1] * scale, acc[mt][nt][0] * scale);
            uint32_t p1 = bf16x2(acc[mt][nt][3] * scale, acc[mt][nt][2] * scale);
            *reinterpret_cast<uint32_t*>(&Out[((size_t)h * NN + n1) * YY + y])     = p0;
            *reinterpret_cast<uint32_t*>(&Out[((size_t)h * NN + n1 + 8) * YY + y]) = p1;
        }
    }
}

// ---------------------------------------------------------------------------
// Fused scores + LSE, split-K (KSPLIT=2). CTA per (qtile 64, head, K-half).
// 4 warps x 16 q-rows. K-chunk 64 rows (16 chunks) -> smem ~19KB -> higher
// residency for latency hiding. Same ascending k order => bitwise-identical.
// grid (32, 12, 2) = 768 CTAs of 128 threads.
// ---------------------------------------------------------------------------
#define ROWB 144
#define S_TILE (KROWS * ROWB)               // 9216 B
#define S_RED  (2 * S_TILE)
#define S_SMEM (S_RED + 128 * 4)            // 18944 B

__global__ void __launch_bounds__(128) scores_kernel(float* __restrict__ out)
{
    extern __shared__ char sm[];
    const uint32_t sb = smem_u32(sm);
    const int tid = threadIdx.x, lane = tid & 31, wid = tid >> 5;
    const int h = blockIdx.y, qt = blockIdx.x, half = blockIdx.z;
    const int grp = h * NQT + qt;

    const __nv_bfloat16* __restrict__ Qsrc = g_Q + ((size_t)h * NN + qt * 64) * YY;
    const __nv_bfloat16* __restrict__ Ksrc = g_K + (size_t)h * NN * YY
                                           + (size_t)half * (NN / KSPLIT) * YY;

    // Q tile 64x64: 512 granules -> 4 per thread; staged across both K buffers
    auto load_q = [&]() {
        #pragma unroll
        for (int i = 0; i < 4; i++) {
            int gi = tid + i * 128;
            int r = gi >> 3, c = gi & 7;
            cpa16(sb + r * ROWB + c * 16, Qsrc + (size_t)r * YY + c * 8);
        }
    };
    // K chunk 64x64: 512 granules -> 4 per thread
    auto load_k = [&](int ch) {
        const int k0 = ch * KROWS;
        const uint32_t buf = sb + (ch & 1) * S_TILE;
        #pragma unroll
        for (int i = 0; i < 4; i++) {
            int gi = tid + i * 128;
            int r = gi >> 3, c = gi & 7;
            cpa16(buf + r * ROWB + c * 16, Ksrc + (size_t)(k0 + r) * YY + c * 8);
        }
    };

    const int lr = lane & 7;
    const uint32_t aoff = (uint32_t)((wid * 16 + lr + ((lane >> 3) & 1) * 8) * ROWB
                                     + ((lane >> 4) & 1) * 16);
    const uint32_t boff = (uint32_t)((lr + ((lane >> 4) & 1) * 8) * ROWB
                                     + ((lane >> 3) & 1) * 16);

    // Stage Q through the two K buffers (64 rows x 144B = fits both), pull
    // fragments into registers, then free them for K.
    load_q(); CP_COMMIT(); CP_WAIT(0);
    __syncthreads();
    uint32_t aR[4][4];
    #pragma unroll
    for (int ks = 0; ks < 4; ks++)
        ldsm4(aR[ks][0], aR[ks][1], aR[ks][2], aR[ks][3], sb + aoff + ks * 32);
    __syncthreads();

    load_k(0); CP_COMMIT();

    float m0 = -INFINITY, l0 = 0.f;   // row a = wid*16 + (lane>>2)
    float m1 = -INFINITY, l1 = 0.f;   // row b = row a + 8

    for (int ch = 0; ch < KCH; ch++) {
        if (ch < KCH - 1) { load_k(ch + 1); CP_COMMIT(); CP_WAIT(1); }
        else CP_WAIT(0);
        __syncthreads();

        const uint32_t bbase = sb + (ch & 1) * S_TILE + boff;
        #pragma unroll
        for (int ntp = 0; ntp < 4; ntp++) {
            float acc[8];
            #pragma unroll
            for (int ks = 0; ks < 4; ks++) {
                uint32_t b0, b1, b2, b3;
                ldsm4(b0, b1, b2, b3, bbase + ntp * 16 * ROWB + ks * 32);
                if (ks == 0) {
                    mma16816_z(acc,     aR[ks], b0, b1);
                    mma16816_z(acc + 4, aR[ks], b2, b3);
                } else {
                    mma16816(acc,     aR[ks], b0, b1);
                    mma16816(acc + 4, aR[ks], b2, b3);
                }
            }
            // rows: acc[0],[1],[4],[5] -> row a ; acc[2],[3],[6],[7] -> row b
            float ca = fmaxf(fmaxf(acc[0], acc[1]), fmaxf(acc[4], acc[5]));
            float cb = fmaxf(fmaxf(acc[2], acc[3]), fmaxf(acc[6], acc[7]));
            if (ca > m0 - 16.0f) {        // flat triggered path, no inner branches
                float mn = fmaxf(m0, ca);
                l0 = l0 * __expf(m0 - mn)
                   + __expf(acc[0] - mn) + __expf(acc[1] - mn)
                   + __expf(acc[4] - mn) + __expf(acc[5] - mn);
                m0 = mn;
            }
            if (cb > m1 - 16.0f) {
                float mn = fmaxf(m1, cb);
                l1 = l1 * __expf(m1 - mn)
                   + __expf(acc[2] - mn) + __expf(acc[3] - mn)
                   + __expf(acc[6] - mn) + __expf(acc[7] - mn);
                m1 = mn;
            }
        }
        __syncthreads();
    }

    // combine the 4 lanes of each quad-row (same row, disjoint k-cols)
    #pragma unroll
    for (int off = 1; off <= 2; off <<= 1) {
        float mo = __shfl_xor_sync(0xffffffffu, m0, off);
        float lo = __shfl_xor_sync(0xffffffffu, l0, off);
        float mm = fmaxf(m0, mo);
        l0 = l0 * __expf(m0 - mm) + lo * __expf(mo - mm);
        m0 = mm;
        mo = __shfl_xor_sync(0xffffffffu, m1, off);
        lo = __shfl_xor_sync(0xffffffffu, l1, off);
        mm = fmaxf(m1, mo);
        l1 = l1 * __expf(m1 - mm) + lo * __expf(mo - mm);
        m1 = mm;
    }

    // publish per-row (m,l) for this half
    float2* gml = g_ml + (size_t)grp * (KSPLIT * 64) + half * 64;
    if ((lane & 3) == 0) {
        int row = wid * 16 + (lane >> 2);
        gml[row]     = make_float2(m0, l0);
        gml[row + 8] = make_float2(m1, l1);
    }
    __threadfence();
    __syncthreads();

    __shared__ unsigned int pos;
    if (tid == 0) pos = atomicAdd(&g_ticket2[grp], 1u);
    __syncthreads();
    if (pos != KSPLIT - 1) return;

    // second finisher: merge halves (deterministic), row LSE, group sum
    float* red = reinterpret_cast<float*>(sm + S_RED);
    {
        float A = 0.f;
        if (tid < 64) {
            const float2* base = g_ml + (size_t)grp * (KSPLIT * 64);
            float2 a = __ldcg(&base[tid]);
            float2 b = __ldcg(&base[64 + tid]);
            float mm = fmaxf(a.x, b.x);
            float L = a.y * __expf(a.x - mm) + b.y * __expf(b.x - mm);
            A = mm + logf(L);
        }
        red[tid] = A;
        __syncthreads();
        if (tid < 32) {
            float s = red[tid] + red[tid + 32];
            #pragma unroll
            for (int off = 16; off > 0; off >>= 1)
                s += __shfl_xor_sync(0xffffffffu, s, off);
            if (tid == 0) g_partial[grp] = s;
        }
    }

    // global last-group election -> final deterministic sum of 384 partials
    __shared__ unsigned int is_last;
    __threadfence();
    if (tid == 0) is_last = (atomicAdd(&g_ticket, 1u) == NGRP - 1);
    __syncthreads();
    if (is_last) {
        __threadfence();
        float s = __ldcg(&g_partial[tid]) + __ldcg(&g_partial[tid + 128])
                + __ldcg(&g_partial[tid + 256]);
        red[tid] = s;
        __syncthreads();
        if (tid < 32) {
            float t = red[tid] + red[tid + 32] + red[tid + 64] + red[tid + 96];
            #pragma unroll
            for (int off = 16; off > 0; off >>= 1)
                t += __shfl_xor_sync(0xffffffffu, t, off);
            if (tid == 0) out[0] = -8.0f * t;
        }
    }
}

extern "C" void kernel_launch(void* const* d_in, const int* in_sizes, int n_in,
                              void* d_out, int out_size)
{
    (void)in_sizes; (void)n_in; (void)out_size;
    const float* g  = (const float*)d_in[0];
    const float* Wq = (const float*)d_in[1];
    const float* Wk = (const float*)d_in[2];
    float* out = (float*)d_out;

    const int convN = NG8 + 2 * NW8;
    conv_kernel<<<(convN + 255) / 256, 256>>>(g, Wq, Wk);
    proj_kernel<<<dim3(6, 32, 2), 128, P_SMEM>>>();
    scores_kernel<<<dim3(NQT, HH, KSPLIT), 128, S_SMEM>>>(out);
}